// round 8
// baseline (speedup 1.0000x reference)
#include <cuda_runtime.h>
#include <math.h>

#define NB 16
#define NH 16
#define LFR 256
#define L 245760
#define NT 15360          // level-0 tiles of 16 per row
#define TWOPI_F 6.28318530717958647692f
#define RINV ((float)(1.0 / 48000.0))   // fl32(1/48000)

__device__ float g_A[NB * NH * LFR];    // exp(amps)
__device__ float g_f0up[NB * L];        // reference-rounded upsampled f0
__device__ float g_E[NB * NH * NT];     // exclusive level-0 tile prefix per row

static __device__ __forceinline__ float fadd(float a, float b) { return __fadd_rn(a, b); }
static __device__ __forceinline__ float fmul(float a, float b) { return __fmul_rn(a, b); }

// reference leaf: fl( fl(f0up * h) * fl(1/48000) )
static __device__ __forceinline__ float leaf(float f0up, float mh) {
    return __fmul_rn(__fmul_rn(f0up, mh), RINV);
}

// reference-exact interp coords for sample t (mul-then-sub, no fma)
static __device__ __forceinline__ void coords(int t, int& i0, int& i1,
                                              float& w, float& omw) {
    const float C960 = (float)(1.0 / 960.0);
    float a = __fadd_rn((float)t, 0.5f);
    float pos = __fsub_rn(__fmul_rn(a, C960), 0.5f);
    pos = fminf(fmaxf(pos, 0.0f), 255.0f);
    i0 = (int)pos;
    i1 = min(i0 + 1, LFR - 1);
    w = __fsub_rn(pos, (float)i0);
    omw = __fsub_rn(1.0f, w);
}

// accurate sin, |theta| < 2^18: Cody-Waite 3-term + deg-11 poly  (VERBATIM R6)
static __device__ __forceinline__ float my_sin(float th) {
    const float I2P = 0.15915494309189533577f;
    const float CA = 6.28125f;
    const float CB = 1.9353071795864769e-3f;
    const float CC = 6.3331253617479151e-11f;
    float k = rintf(__fmul_rn(th, I2P));
    float r = __fmaf_rn(-k, CA, th);
    r = __fmaf_rn(-k, CB, r);
    r = __fmaf_rn(-k, CC, r);
    const float PI_F = 3.14159265358979323846f;
    const float PIH = 1.57079632679489661923f;
    if (r > PIH) r = __fsub_rn(PI_F, r);
    else if (r < -PIH) r = __fsub_rn(-PI_F, r);
    float r2 = __fmul_rn(r, r);
    float p = -2.50521084e-8f;
    p = __fmaf_rn(p, r2, 2.75573192e-6f);
    p = __fmaf_rn(p, r2, -1.98412698e-4f);
    p = __fmaf_rn(p, r2, 8.33333333e-3f);
    p = __fmaf_rn(p, r2, -1.66666667e-1f);
    return __fmaf_rn(__fmul_rn(p, r2), r, r);
}

// ---------------------------------------------------------------------------
__global__ void __launch_bounds__(256) prep_exp(const float* __restrict__ amps) {
    int i = blockIdx.x * 256 + threadIdx.x;
    if (i < NB * NH * LFR) g_A[i] = expf(amps[i]);
}

__global__ void __launch_bounds__(256) f0up_kernel(const float* __restrict__ f0) {
    __shared__ float sf0[LFR];
    int n = blockIdx.y;
    int tid = threadIdx.x;
    if (tid < LFR) sf0[tid] = fmaxf(f0[n * LFR + tid], 20.0f);
    __syncthreads();
    int t = blockIdx.x * 256 + tid;
    int i0, i1; float w, omw;
    coords(t, i0, i1, w, omw);
    g_f0up[n * L + t] = fadd(fmul(sf0[i0], omw), fmul(sf0[i1], w));
}

// ---------------------------------------------------------------------------
// One block per row (n,h): XLA ReduceWindowRewriter (base 16) emulation,
// reading memoized f0up. fp op sequence VERBATIM R6.
// ---------------------------------------------------------------------------
__global__ void __launch_bounds__(960) rowscan_kernel() {
    __shared__ float s1[960];
    __shared__ float in2[960];
    __shared__ float r2s[960];
    __shared__ float s2[60];
    __shared__ float in3[64];
    __shared__ float s3[4];
    __shared__ float r4[4];
    __shared__ float r3[64];
    int row = blockIdx.x;
    int n = row >> 4;
    float mh = (float)((row & 15) + 1);
    int tid = threadIdx.x;

    const float4* fp = (const float4*)(g_f0up + n * L) + tid * 64;
    float pref1[16];
    float acc1 = 0.0f;
#pragma unroll
    for (int ss = 0; ss < 16; ss++) {
        float a = 0.0f;
#pragma unroll
        for (int s4 = 0; s4 < 4; s4++) {
            float4 v = fp[ss * 4 + s4];
            a = fadd(a, leaf(v.x, mh));
            a = fadd(a, leaf(v.y, mh));
            a = fadd(a, leaf(v.z, mh));
            a = fadd(a, leaf(v.w, mh));
        }
        acc1 = fadd(acc1, a);
        pref1[ss] = acc1;
    }
    s1[tid] = acc1;
    __syncthreads();

    if (tid < 60) {
        float a = 0.0f;
#pragma unroll
        for (int s = 0; s < 16; s++) { a = fadd(a, s1[tid * 16 + s]); in2[tid * 16 + s] = a; }
        s2[tid] = a;
    }
    __syncthreads();
    if (tid < 4) {
        float a = 0.0f;
#pragma unroll
        for (int s = 0; s < 16; s++) {
            int i = tid * 16 + s;
            float v = (i < 60) ? s2[i] : 0.0f;
            a = fadd(a, v);
            in3[i] = a;
        }
        s3[tid] = a;
    }
    __syncthreads();
    if (tid == 0) {
        float a = 0.0f;
#pragma unroll
        for (int p = 0; p < 4; p++) { a = fadd(a, s3[p]); r4[p] = a; }
    }
    __syncthreads();
    if (tid < 64)
        r3[tid] = (tid < 16) ? in3[tid] : fadd(in3[tid], r4[(tid >> 4) - 1]);
    __syncthreads();
    r2s[tid] = (tid < 16) ? in2[tid] : fadd(in2[tid], r3[(tid >> 4) - 1]);
    __syncthreads();

    float E2 = (tid == 0) ? 0.0f : r2s[tid - 1];
    float* Erow = g_E + row * NT;
    if (tid == 0) Erow[0] = 0.0f;
#pragma unroll
    for (int ss = 0; ss < 16; ss++) {
        int q = tid * 16 + ss;
        float r1 = fadd(pref1[ss], E2);
        if (q + 1 < NT) Erow[q + 1] = r1;
    }
}

// ---------------------------------------------------------------------------
// Oscillator: thread per (n, level-0 tile). fp sequence VERBATIM R6; i0/i1,
// v0/v1, a0[h]/a1[h] hoisted per tile (constant: segment boundaries land on
// multiples of 16). smem-staged coalesced stores.
// ---------------------------------------------------------------------------
__global__ void __launch_bounds__(256) osc_kernel(const float* __restrict__ f0raw,
                                                  float* __restrict__ out) {
    __shared__ float sA[NH * LFR];
    __shared__ float sf0[LFR];
    __shared__ float stage[256 * 17];
    int n = blockIdx.y;
    int tid = threadIdx.x;
    {
        const float4* src = (const float4*)(g_A + n * NH * LFR);
        float4* dst = (float4*)sA;
        for (int i = tid; i < NH * LFR / 4; i += 256) dst[i] = src[i];
    }
    if (tid < LFR) sf0[tid] = fmaxf(f0raw[n * LFR + tid], 20.0f);
    __syncthreads();

    int q = blockIdx.x * 256 + tid;
    int t0 = q * 16;

    int i0, i1; float w0, omw0;
    coords(t0, i0, i1, w0, omw0);
    float i0f = (float)i0;
    float v0 = sf0[i0], v1 = sf0[i1];

    float a0[NH], a1[NH], run[NH], Ev[NH];
#pragma unroll
    for (int h = 0; h < NH; h++) {
        a0[h] = sA[h * LFR + i0];
        a1[h] = sA[h * LFR + i1];
        run[h] = 0.0f;
        Ev[h] = g_E[((n << 4) + h) * NT + q];
    }
    const float C960 = (float)(1.0 / 960.0);

#pragma unroll
    for (int s = 0; s < 16; s++) {
        int t = t0 + s;
        float a = __fadd_rn((float)t, 0.5f);
        float pos = __fsub_rn(__fmul_rn(a, C960), 0.5f);
        pos = fminf(fmaxf(pos, 0.0f), 255.0f);
        float w = __fsub_rn(pos, i0f);
        float omw = __fsub_rn(1.0f, w);
        float f0u = fadd(fmul(v0, omw), fmul(v1, w));
        float wave = 0.0f;
#pragma unroll
        for (int h = 0; h < NH; h++) {
            float lv = leaf(f0u, (float)(h + 1));
            run[h] = fadd(run[h], lv);
            float dt = fadd(run[h], Ev[h]);
            float theta = __fmul_rn(TWOPI_F, dt);
            float sv = my_sin(theta);
            float amp = fadd(fmul(a0[h], omw), fmul(a1[h], w));
            wave = fadd(wave, fmul(sv, amp));
        }
        stage[tid * 17 + s] = __fmul_rn(wave, 0.0625f);
    }
    __syncthreads();

    float* obase = out + n * L + blockIdx.x * 4096;
    for (int i = tid; i < 4096; i += 256)
        obase[i] = stage[(i >> 4) * 17 + (i & 15)];
}

// ---------------------------------------------------------------------------
extern "C" void kernel_launch(void* const* d_in, const int* in_sizes, int n_in,
                              void* d_out, int out_size) {
    const float* amps = (const float*)d_in[0];
    const float* f0 = (const float*)d_in[1];
    if (n_in >= 2 && in_sizes[0] == NB * LFR && in_sizes[1] == NB * NH * LFR) {
        const float* tmp = amps; amps = f0; f0 = tmp;
    }
    float* out = (float*)d_out;

    prep_exp<<<(NB * NH * LFR + 255) / 256, 256>>>(amps);
    f0up_kernel<<<dim3(L / 256, NB), 256>>>(f0);
    rowscan_kernel<<<NB * NH, 960>>>();
    osc_kernel<<<dim3(NT / 256, NB), 256>>>(f0, out);
}

// round 9
// speedup vs baseline: 3.0417x; 3.0417x over previous
#include <cuda_runtime.h>
#include <math.h>

#define NB 16
#define NH 16
#define LFR 256
#define L 245760
#define NT 15360          // level-0 tiles (16 samples) per row
#define NJ 960            // level-1 tiles (256 samples) per row
#define TWOPI_F 6.28318530717958647692f
#define RINV ((float)(1.0 / 48000.0))   // fl32(1/48000)

__device__ float g_A[NB * NH * LFR];    // exp(amps)
__device__ float g_f0up[NB * L];        // reference-rounded upsampled f0
__device__ float g_P1[NB * NT * NH];    // inclusive level-1 prefixes, [n][q][h]
__device__ float g_S1[NB * NH * NJ];    // level-1 sums, [row][j]
__device__ float g_E2t[NB * NJ * NH];   // exclusive level-2 prefixes, [n][j][h]

static __device__ __forceinline__ float fadd(float a, float b) { return __fadd_rn(a, b); }
static __device__ __forceinline__ float fmul(float a, float b) { return __fmul_rn(a, b); }

// reference leaf: fl( fl(f0up * h) * fl(1/48000) )
static __device__ __forceinline__ float leaf(float f0up, float mh) {
    return __fmul_rn(__fmul_rn(f0up, mh), RINV);
}

// reference-exact interp coords for sample t (mul-then-sub, no fma)
static __device__ __forceinline__ void coords(int t, int& i0, int& i1,
                                              float& w, float& omw) {
    const float C960 = (float)(1.0 / 960.0);
    float a = __fadd_rn((float)t, 0.5f);
    float pos = __fsub_rn(__fmul_rn(a, C960), 0.5f);
    pos = fminf(fmaxf(pos, 0.0f), 255.0f);
    i0 = (int)pos;
    i1 = min(i0 + 1, LFR - 1);
    w = __fsub_rn(pos, (float)i0);
    omw = __fsub_rn(1.0f, w);
}

// accurate sin, |theta| < 2^18: Cody-Waite 3-term + deg-11 poly  (VERBATIM R6)
static __device__ __forceinline__ float my_sin(float th) {
    const float I2P = 0.15915494309189533577f;
    const float CA = 6.28125f;
    const float CB = 1.9353071795864769e-3f;
    const float CC = 6.3331253617479151e-11f;
    float k = rintf(__fmul_rn(th, I2P));
    float r = __fmaf_rn(-k, CA, th);
    r = __fmaf_rn(-k, CB, r);
    r = __fmaf_rn(-k, CC, r);
    const float PI_F = 3.14159265358979323846f;
    const float PIH = 1.57079632679489661923f;
    if (r > PIH) r = __fsub_rn(PI_F, r);
    else if (r < -PIH) r = __fsub_rn(-PI_F, r);
    float r2 = __fmul_rn(r, r);
    float p = -2.50521084e-8f;
    p = __fmaf_rn(p, r2, 2.75573192e-6f);
    p = __fmaf_rn(p, r2, -1.98412698e-4f);
    p = __fmaf_rn(p, r2, 8.33333333e-3f);
    p = __fmaf_rn(p, r2, -1.66666667e-1f);
    return __fmaf_rn(__fmul_rn(p, r2), r, r);
}

// ---------------------------------------------------------------------------
__global__ void __launch_bounds__(256) prep_exp(const float* __restrict__ amps) {
    int i = blockIdx.x * 256 + threadIdx.x;
    if (i < NB * NH * LFR) g_A[i] = expf(amps[i]);
}

__global__ void __launch_bounds__(256) f0up_kernel(const float* __restrict__ f0) {
    __shared__ float sf0[LFR];
    int n = blockIdx.y;
    int tid = threadIdx.x;
    if (tid < LFR) sf0[tid] = fmaxf(f0[n * LFR + tid], 20.0f);
    __syncthreads();
    int t = blockIdx.x * 256 + tid;
    int i0, i1; float w, omw;
    coords(t, i0, i1, w, omw);
    g_f0up[n * L + t] = fadd(fmul(sf0[i0], omw), fmul(sf0[i1], w));
}

// ---------------------------------------------------------------------------
// scan1: grid (60, NB), block 256 = 16 level-1 tiles x 16 harmonics.
// Stages a 4096-sample chunk of f0up in smem (coalesced), then each thread
// does the serial level-0/level-1 fold for one (level-1 tile, h), VERBATIM
// fold order. Writes transposed P1[n][q][h] and S1[row][j].
// ---------------------------------------------------------------------------
__global__ void __launch_bounds__(256) scan1_kernel() {
    __shared__ float smf[4096];
    int n = blockIdx.y;
    int tid = threadIdx.x;
    int jl = tid >> 4;          // level-1 tile within chunk
    int h = tid & 15;
    int jg = blockIdx.x * 16 + jl;

    {
        const float4* src = (const float4*)(g_f0up + n * L + blockIdx.x * 4096);
        float4* dst = (float4*)smf;
        for (int i = tid; i < 1024; i += 256) dst[i] = src[i];
    }
    __syncthreads();

    float mh = (float)(h + 1);
    const float* base = smf + jl * 256;
    float acc1 = 0.0f;
#pragma unroll
    for (int ss = 0; ss < 16; ss++) {
        float a = 0.0f;
#pragma unroll
        for (int s = 0; s < 16; s++)
            a = fadd(a, leaf(base[ss * 16 + s], mh));
        acc1 = fadd(acc1, a);
        g_P1[((n * NT + jg * 16 + ss) << 4) + h] = acc1;
    }
    g_S1[(n * 16 + h) * NJ + jg] = acc1;
}

// ---------------------------------------------------------------------------
// scan2: one block per row (n,h); levels 2..4 VERBATIM R8 from S1; emits
// exclusive level-2 prefix per level-1 tile into E2t[n][j][h].
// ---------------------------------------------------------------------------
__global__ void __launch_bounds__(960) scan2_kernel() {
    __shared__ float s1[960];
    __shared__ float in2[960];
    __shared__ float r2s[960];
    __shared__ float s2[60];
    __shared__ float in3[64];
    __shared__ float s3[4];
    __shared__ float r4[4];
    __shared__ float r3[64];
    int row = blockIdx.x;
    int n = row >> 4, h = row & 15;
    int tid = threadIdx.x;

    s1[tid] = g_S1[row * NJ + tid];
    __syncthreads();

    if (tid < 60) {
        float a = 0.0f;
#pragma unroll
        for (int s = 0; s < 16; s++) { a = fadd(a, s1[tid * 16 + s]); in2[tid * 16 + s] = a; }
        s2[tid] = a;
    }
    __syncthreads();
    if (tid < 4) {
        float a = 0.0f;
#pragma unroll
        for (int s = 0; s < 16; s++) {
            int i = tid * 16 + s;
            float v = (i < 60) ? s2[i] : 0.0f;
            a = fadd(a, v);
            in3[i] = a;
        }
        s3[tid] = a;
    }
    __syncthreads();
    if (tid == 0) {
        float a = 0.0f;
#pragma unroll
        for (int p = 0; p < 4; p++) { a = fadd(a, s3[p]); r4[p] = a; }
    }
    __syncthreads();
    if (tid < 64)
        r3[tid] = (tid < 16) ? in3[tid] : fadd(in3[tid], r4[(tid >> 4) - 1]);
    __syncthreads();
    r2s[tid] = (tid < 16) ? in2[tid] : fadd(in2[tid], r3[(tid >> 4) - 1]);
    __syncthreads();

    float E2 = (tid == 0) ? 0.0f : r2s[tid - 1];
    g_E2t[((n * NJ + tid) << 4) + h] = E2;
}

// ---------------------------------------------------------------------------
// Oscillator: 4 threads per level-0 tile, 4 harmonics each. Ev reconstructed
// as fadd(P1[n][q-1][h], E2t[n][(q-1)>>4][h]) — bit-identical to old E[q].
// Per-sample 16-h sum: serial quad + 2x shfl_xor pairwise combine (final,
// non-amplified reduction). Coalesced staged stores.
// ---------------------------------------------------------------------------
__global__ void __launch_bounds__(256) osc_kernel(const float* __restrict__ f0raw,
                                                  float* __restrict__ out) {
    __shared__ float sA[NH * LFR];
    __shared__ float sf0[LFR];
    __shared__ float stage[64 * 17];
    int n = blockIdx.y;
    int tid = threadIdx.x;
    {
        const float4* src = (const float4*)(g_A + n * NH * LFR);
        float4* dst = (float4*)sA;
        for (int i = tid; i < NH * LFR / 4; i += 256) dst[i] = src[i];
    }
    if (tid < LFR) sf0[tid] = fmaxf(f0raw[n * LFR + tid], 20.0f);
    __syncthreads();

    int ql = tid >> 2;          // tile within block (0..63)
    int hq = tid & 3;           // harmonic quad (h = 4*hq .. 4*hq+3)
    int q = blockIdx.x * 64 + ql;
    int t0 = q * 16;

    int i0, i1; float w0, omw0;
    coords(t0, i0, i1, w0, omw0);
    float i0f = (float)i0;
    float v0 = sf0[i0], v1 = sf0[i1];

    float Ev[4], run[4], a0[4], a1[4];
    if (q == 0) {
#pragma unroll
        for (int i = 0; i < 4; i++) Ev[i] = 0.0f;
    } else {
        float4 p1 = *(const float4*)&g_P1[((n * NT + q - 1) << 4) + hq * 4];
        float4 e2 = *(const float4*)&g_E2t[((n * NJ + ((q - 1) >> 4)) << 4) + hq * 4];
        Ev[0] = fadd(p1.x, e2.x);
        Ev[1] = fadd(p1.y, e2.y);
        Ev[2] = fadd(p1.z, e2.z);
        Ev[3] = fadd(p1.w, e2.w);
    }
#pragma unroll
    for (int i = 0; i < 4; i++) {
        int h = hq * 4 + i;
        a0[i] = sA[h * LFR + i0];
        a1[i] = sA[h * LFR + i1];
        run[i] = 0.0f;
    }
    float mh0 = (float)(hq * 4 + 1);
    const float C960 = (float)(1.0 / 960.0);

#pragma unroll
    for (int s = 0; s < 16; s++) {
        int t = t0 + s;
        float a = __fadd_rn((float)t, 0.5f);
        float pos = __fsub_rn(__fmul_rn(a, C960), 0.5f);
        pos = fminf(fmaxf(pos, 0.0f), 255.0f);
        float w = __fsub_rn(pos, i0f);
        float omw = __fsub_rn(1.0f, w);
        float f0u = fadd(fmul(v0, omw), fmul(v1, w));
        float part = 0.0f;
#pragma unroll
        for (int i = 0; i < 4; i++) {
            float mh = mh0 + (float)i;           // exact small ints
            float lv = leaf(f0u, mh);
            run[i] = fadd(run[i], lv);
            float dt = fadd(run[i], Ev[i]);
            float theta = __fmul_rn(TWOPI_F, dt);
            float sv = my_sin(theta);
            float amp = fadd(fmul(a0[i], omw), fmul(a1[i], w));
            part = fadd(part, fmul(sv, amp));
        }
        part = fadd(part, __shfl_xor_sync(0xffffffffu, part, 1));
        part = fadd(part, __shfl_xor_sync(0xffffffffu, part, 2));
        if (hq == 0) stage[ql * 17 + s] = __fmul_rn(part, 0.0625f);
    }
    __syncthreads();

    float* obase = out + n * L + blockIdx.x * 1024;
    for (int i = tid; i < 1024; i += 256)
        obase[i] = stage[(i >> 4) * 17 + (i & 15)];
}

// ---------------------------------------------------------------------------
extern "C" void kernel_launch(void* const* d_in, const int* in_sizes, int n_in,
                              void* d_out, int out_size) {
    const float* amps = (const float*)d_in[0];
    const float* f0 = (const float*)d_in[1];
    if (n_in >= 2 && in_sizes[0] == NB * LFR && in_sizes[1] == NB * NH * LFR) {
        const float* tmp = amps; amps = f0; f0 = tmp;
    }
    float* out = (float*)d_out;

    prep_exp<<<(NB * NH * LFR + 255) / 256, 256>>>(amps);
    f0up_kernel<<<dim3(L / 256, NB), 256>>>(f0);
    scan1_kernel<<<dim3(NJ / 16, NB), 256>>>();
    scan2_kernel<<<NB * NH, 960>>>();
    osc_kernel<<<dim3(NT / 64, NB), 256>>>(f0, out);
}

// round 10
// speedup vs baseline: 4.5023x; 1.4802x over previous
#include <cuda_runtime.h>
#include <math.h>

#define NB 16
#define NH 16
#define LFR 256
#define L 245760
#define NT 15360          // level-0 tiles (16 samples) per row
#define NJ 960            // level-1 tiles (256 samples) per row
#define TWOPI_F 6.28318530717958647692f
#define RINV ((float)(1.0 / 48000.0))   // fl32(1/48000)

__device__ float g_A[NB * NH * LFR];    // exp(amps)
__device__ float g_f0up[NB * L];        // reference-rounded upsampled f0
__device__ float g_P1[NB * NT * NH];    // inclusive level-1 prefixes, [n][q][h]
__device__ float g_S1[NB * NH * NJ];    // level-1 sums, [row][j]
__device__ float g_E2t[NB * NJ * NH];   // exclusive level-2 prefixes, [n][j][h]

static __device__ __forceinline__ float fadd(float a, float b) { return __fadd_rn(a, b); }
static __device__ __forceinline__ float fmul(float a, float b) { return __fmul_rn(a, b); }

// reference leaf: fl( fl(f0up * h) * fl(1/48000) )
static __device__ __forceinline__ float leaf(float f0up, float mh) {
    return __fmul_rn(__fmul_rn(f0up, mh), RINV);
}

// reference-exact interp coords for sample t (mul-then-sub, no fma)
static __device__ __forceinline__ void coords(int t, int& i0, int& i1,
                                              float& w, float& omw) {
    const float C960 = (float)(1.0 / 960.0);
    float a = __fadd_rn((float)t, 0.5f);
    float pos = __fsub_rn(__fmul_rn(a, C960), 0.5f);
    pos = fminf(fmaxf(pos, 0.0f), 255.0f);
    i0 = (int)pos;
    i1 = min(i0 + 1, LFR - 1);
    w = __fsub_rn(pos, (float)i0);
    omw = __fsub_rn(1.0f, w);
}

// sin: 3-term Cody-Waite reduction (VERBATIM R9) -> |r| <= pi -> MUFU __sinf
// (A/B vs R9: ONLY the polynomial tail replaced by __sinf.)
static __device__ __forceinline__ float my_sin(float th) {
    const float I2P = 0.15915494309189533577f;
    const float CA = 6.28125f;
    const float CB = 1.9353071795864769e-3f;
    const float CC = 6.3331253617479151e-11f;
    float k = rintf(__fmul_rn(th, I2P));
    float r = __fmaf_rn(-k, CA, th);
    r = __fmaf_rn(-k, CB, r);
    r = __fmaf_rn(-k, CC, r);
    return __sinf(r);
}

// ---------------------------------------------------------------------------
__global__ void __launch_bounds__(256) prep_exp(const float* __restrict__ amps) {
    int i = blockIdx.x * 256 + threadIdx.x;
    if (i < NB * NH * LFR) g_A[i] = expf(amps[i]);
}

__global__ void __launch_bounds__(256) f0up_kernel(const float* __restrict__ f0) {
    __shared__ float sf0[LFR];
    int n = blockIdx.y;
    int tid = threadIdx.x;
    if (tid < LFR) sf0[tid] = fmaxf(f0[n * LFR + tid], 20.0f);
    __syncthreads();
    int t = blockIdx.x * 256 + tid;
    int i0, i1; float w, omw;
    coords(t, i0, i1, w, omw);
    g_f0up[n * L + t] = fadd(fmul(sf0[i0], omw), fmul(sf0[i1], w));
}

// ---------------------------------------------------------------------------
// scan1: grid (60, NB), block 256 = 16 level-1 tiles x 16 harmonics.
// Stages a 4096-sample chunk of f0up in smem (coalesced), then each thread
// does the serial level-0/level-1 fold for one (level-1 tile, h), VERBATIM
// fold order. Writes transposed P1[n][q][h] and S1[row][j].
// ---------------------------------------------------------------------------
__global__ void __launch_bounds__(256) scan1_kernel() {
    __shared__ float smf[4096];
    int n = blockIdx.y;
    int tid = threadIdx.x;
    int jl = tid >> 4;          // level-1 tile within chunk
    int h = tid & 15;
    int jg = blockIdx.x * 16 + jl;

    {
        const float4* src = (const float4*)(g_f0up + n * L + blockIdx.x * 4096);
        float4* dst = (float4*)smf;
        for (int i = tid; i < 1024; i += 256) dst[i] = src[i];
    }
    __syncthreads();

    float mh = (float)(h + 1);
    const float* base = smf + jl * 256;
    float acc1 = 0.0f;
#pragma unroll
    for (int ss = 0; ss < 16; ss++) {
        float a = 0.0f;
#pragma unroll
        for (int s = 0; s < 16; s++)
            a = fadd(a, leaf(base[ss * 16 + s], mh));
        acc1 = fadd(acc1, a);
        g_P1[((n * NT + jg * 16 + ss) << 4) + h] = acc1;
    }
    g_S1[(n * 16 + h) * NJ + jg] = acc1;
}

// ---------------------------------------------------------------------------
// scan2: one block per row (n,h); levels 2..4 VERBATIM from S1; emits
// exclusive level-2 prefix per level-1 tile into E2t[n][j][h].
// ---------------------------------------------------------------------------
__global__ void __launch_bounds__(960) scan2_kernel() {
    __shared__ float s1[960];
    __shared__ float in2[960];
    __shared__ float r2s[960];
    __shared__ float s2[60];
    __shared__ float in3[64];
    __shared__ float s3[4];
    __shared__ float r4[4];
    __shared__ float r3[64];
    int row = blockIdx.x;
    int n = row >> 4, h = row & 15;
    int tid = threadIdx.x;

    s1[tid] = g_S1[row * NJ + tid];
    __syncthreads();

    if (tid < 60) {
        float a = 0.0f;
#pragma unroll
        for (int s = 0; s < 16; s++) { a = fadd(a, s1[tid * 16 + s]); in2[tid * 16 + s] = a; }
        s2[tid] = a;
    }
    __syncthreads();
    if (tid < 4) {
        float a = 0.0f;
#pragma unroll
        for (int s = 0; s < 16; s++) {
            int i = tid * 16 + s;
            float v = (i < 60) ? s2[i] : 0.0f;
            a = fadd(a, v);
            in3[i] = a;
        }
        s3[tid] = a;
    }
    __syncthreads();
    if (tid == 0) {
        float a = 0.0f;
#pragma unroll
        for (int p = 0; p < 4; p++) { a = fadd(a, s3[p]); r4[p] = a; }
    }
    __syncthreads();
    if (tid < 64)
        r3[tid] = (tid < 16) ? in3[tid] : fadd(in3[tid], r4[(tid >> 4) - 1]);
    __syncthreads();
    r2s[tid] = (tid < 16) ? in2[tid] : fadd(in2[tid], r3[(tid >> 4) - 1]);
    __syncthreads();

    float E2 = (tid == 0) ? 0.0f : r2s[tid - 1];
    g_E2t[((n * NJ + tid) << 4) + h] = E2;
}

// ---------------------------------------------------------------------------
// Oscillator: 4 threads per level-0 tile, 4 harmonics each. Ev reconstructed
// as fadd(P1[n][q-1][h], E2t[n][(q-1)>>4][h]) — bit-identical to old E[q].
// Per-sample 16-h sum: serial quad + 2x shfl_xor pairwise combine.
// ---------------------------------------------------------------------------
__global__ void __launch_bounds__(256) osc_kernel(const float* __restrict__ f0raw,
                                                  float* __restrict__ out) {
    __shared__ float sA[NH * LFR];
    __shared__ float sf0[LFR];
    __shared__ float stage[64 * 17];
    int n = blockIdx.y;
    int tid = threadIdx.x;
    {
        const float4* src = (const float4*)(g_A + n * NH * LFR);
        float4* dst = (float4*)sA;
        for (int i = tid; i < NH * LFR / 4; i += 256) dst[i] = src[i];
    }
    if (tid < LFR) sf0[tid] = fmaxf(f0raw[n * LFR + tid], 20.0f);
    __syncthreads();

    int ql = tid >> 2;          // tile within block (0..63)
    int hq = tid & 3;           // harmonic quad (h = 4*hq .. 4*hq+3)
    int q = blockIdx.x * 64 + ql;
    int t0 = q * 16;

    int i0, i1; float w0, omw0;
    coords(t0, i0, i1, w0, omw0);
    float i0f = (float)i0;
    float v0 = sf0[i0], v1 = sf0[i1];

    float Ev[4], run[4], a0[4], a1[4];
    if (q == 0) {
#pragma unroll
        for (int i = 0; i < 4; i++) Ev[i] = 0.0f;
    } else {
        float4 p1 = *(const float4*)&g_P1[((n * NT + q - 1) << 4) + hq * 4];
        float4 e2 = *(const float4*)&g_E2t[((n * NJ + ((q - 1) >> 4)) << 4) + hq * 4];
        Ev[0] = fadd(p1.x, e2.x);
        Ev[1] = fadd(p1.y, e2.y);
        Ev[2] = fadd(p1.z, e2.z);
        Ev[3] = fadd(p1.w, e2.w);
    }
#pragma unroll
    for (int i = 0; i < 4; i++) {
        int h = hq * 4 + i;
        a0[i] = sA[h * LFR + i0];
        a1[i] = sA[h * LFR + i1];
        run[i] = 0.0f;
    }
    float mh0 = (float)(hq * 4 + 1);
    const float C960 = (float)(1.0 / 960.0);

#pragma unroll
    for (int s = 0; s < 16; s++) {
        int t = t0 + s;
        float a = __fadd_rn((float)t, 0.5f);
        float pos = __fsub_rn(__fmul_rn(a, C960), 0.5f);
        pos = fminf(fmaxf(pos, 0.0f), 255.0f);
        float w = __fsub_rn(pos, i0f);
        float omw = __fsub_rn(1.0f, w);
        float f0u = fadd(fmul(v0, omw), fmul(v1, w));
        float part = 0.0f;
#pragma unroll
        for (int i = 0; i < 4; i++) {
            float mh = mh0 + (float)i;           // exact small ints
            float lv = leaf(f0u, mh);
            run[i] = fadd(run[i], lv);
            float dt = fadd(run[i], Ev[i]);
            float theta = __fmul_rn(TWOPI_F, dt);
            float sv = my_sin(theta);
            float amp = fadd(fmul(a0[i], omw), fmul(a1[i], w));
            part = fadd(part, fmul(sv, amp));
        }
        part = fadd(part, __shfl_xor_sync(0xffffffffu, part, 1));
        part = fadd(part, __shfl_xor_sync(0xffffffffu, part, 2));
        if (hq == 0) stage[ql * 17 + s] = __fmul_rn(part, 0.0625f);
    }
    __syncthreads();

    float* obase = out + n * L + blockIdx.x * 1024;
    for (int i = tid; i < 1024; i += 256)
        obase[i] = stage[(i >> 4) * 17 + (i & 15)];
}

// ---------------------------------------------------------------------------
extern "C" void kernel_launch(void* const* d_in, const int* in_sizes, int n_in,
                              void* d_out, int out_size) {
    const float* amps = (const float*)d_in[0];
    const float* f0 = (const float*)d_in[1];
    if (n_in >= 2 && in_sizes[0] == NB * LFR && in_sizes[1] == NB * NH * LFR) {
        const float* tmp = amps; amps = f0; f0 = tmp;
    }
    float* out = (float*)d_out;

    prep_exp<<<(NB * NH * LFR + 255) / 256, 256>>>(amps);
    f0up_kernel<<<dim3(L / 256, NB), 256>>>(f0);
    scan1_kernel<<<dim3(NJ / 16, NB), 256>>>();
    scan2_kernel<<<NB * NH, 960>>>();
    osc_kernel<<<dim3(NT / 64, NB), 256>>>(f0, out);
}

// round 11
// speedup vs baseline: 5.3253x; 1.1828x over previous
#include <cuda_runtime.h>
#include <math.h>

#define NB 16
#define NH 16
#define LFR 256
#define L 245760
#define NT 15360          // level-0 tiles (16 samples) per row
#define NJ 960            // level-1 tiles (256 samples) per row
#define TWOPI_F 6.28318530717958647692f
#define RINV ((float)(1.0 / 48000.0))   // fl32(1/48000)
#define CW_A 6.28125f
#define CW_B 1.9353071795864769e-3f
#define CW_C 6.3331253617479151e-11f

__device__ float g_A[NB * NH * LFR];    // exp(amps)
__device__ float g_P1[NB * NT * NH];    // inclusive level-1 prefixes, [n][q][h]
__device__ float g_S1[NB * NH * NJ];    // level-1 sums, [row][j]
__device__ float g_E2t[NB * NJ * NH];   // exclusive level-2 prefixes, [n][j][h]

static __device__ __forceinline__ float fadd(float a, float b) { return __fadd_rn(a, b); }
static __device__ __forceinline__ float fmul(float a, float b) { return __fmul_rn(a, b); }

// reference leaf: fl( fl(f0up * h) * fl(1/48000) )
static __device__ __forceinline__ float leaf(float f0up, float mh) {
    return __fmul_rn(__fmul_rn(f0up, mh), RINV);
}

// reference-exact interp coords for sample t (mul-then-sub, no fma)
static __device__ __forceinline__ void coords(int t, int& i0, int& i1,
                                              float& w, float& omw) {
    const float C960 = (float)(1.0 / 960.0);
    float a = __fadd_rn((float)t, 0.5f);
    float pos = __fsub_rn(__fmul_rn(a, C960), 0.5f);
    pos = fminf(fmaxf(pos, 0.0f), 255.0f);
    i0 = (int)pos;
    i1 = min(i0 + 1, LFR - 1);
    w = __fsub_rn(pos, (float)i0);
    omw = __fsub_rn(1.0f, w);
}

// ---------------------------------------------------------------------------
__global__ void __launch_bounds__(256) prep_exp(const float* __restrict__ amps) {
    int i = blockIdx.x * 256 + threadIdx.x;
    if (i < NB * NH * LFR) g_A[i] = expf(amps[i]);
}

// ---------------------------------------------------------------------------
// scan1: grid (60, NB), block 256 = 16 level-1 tiles x 16 harmonics.
// Computes the 4096-sample f0up chunk into smem (bit-identical formula),
// then each thread serially folds level-0/level-1 for one (tile, h),
// fold order VERBATIM. Writes transposed P1[n][q][h] and S1[row][j].
// ---------------------------------------------------------------------------
__global__ void __launch_bounds__(256) scan1_kernel(const float* __restrict__ f0raw) {
    __shared__ float sf0[LFR];
    __shared__ float smf[4096];
    int n = blockIdx.y;
    int tid = threadIdx.x;
    int baset = blockIdx.x * 4096;

    if (tid < LFR) sf0[tid] = fmaxf(f0raw[n * LFR + tid], 20.0f);
    __syncthreads();
    for (int i = tid; i < 4096; i += 256) {
        int t = baset + i;
        int i0, i1; float w, omw;
        coords(t, i0, i1, w, omw);
        smf[i] = fadd(fmul(sf0[i0], omw), fmul(sf0[i1], w));
    }
    __syncthreads();

    int jl = tid >> 4;          // level-1 tile within chunk
    int h = tid & 15;
    int jg = blockIdx.x * 16 + jl;
    float mh = (float)(h + 1);
    const float* base = smf + jl * 256;
    float acc1 = 0.0f;
#pragma unroll
    for (int ss = 0; ss < 16; ss++) {
        float a = 0.0f;
#pragma unroll
        for (int s = 0; s < 16; s++)
            a = fadd(a, leaf(base[ss * 16 + s], mh));
        acc1 = fadd(acc1, a);
        g_P1[((n * NT + jg * 16 + ss) << 4) + h] = acc1;
    }
    g_S1[(n * 16 + h) * NJ + jg] = acc1;
}

// ---------------------------------------------------------------------------
// scan2: one block per row (n,h); levels 2..4 VERBATIM from S1; emits
// exclusive level-2 prefix per level-1 tile into E2t[n][j][h].
// ---------------------------------------------------------------------------
__global__ void __launch_bounds__(960) scan2_kernel() {
    __shared__ float s1[960];
    __shared__ float in2[960];
    __shared__ float r2s[960];
    __shared__ float s2[60];
    __shared__ float in3[64];
    __shared__ float s3[4];
    __shared__ float r4[4];
    __shared__ float r3[64];
    int row = blockIdx.x;
    int n = row >> 4, h = row & 15;
    int tid = threadIdx.x;

    s1[tid] = g_S1[row * NJ + tid];
    __syncthreads();

    if (tid < 60) {
        float a = 0.0f;
#pragma unroll
        for (int s = 0; s < 16; s++) { a = fadd(a, s1[tid * 16 + s]); in2[tid * 16 + s] = a; }
        s2[tid] = a;
    }
    __syncthreads();
    if (tid < 4) {
        float a = 0.0f;
#pragma unroll
        for (int s = 0; s < 16; s++) {
            int i = tid * 16 + s;
            float v = (i < 60) ? s2[i] : 0.0f;
            a = fadd(a, v);
            in3[i] = a;
        }
        s3[tid] = a;
    }
    __syncthreads();
    if (tid == 0) {
        float a = 0.0f;
#pragma unroll
        for (int p = 0; p < 4; p++) { a = fadd(a, s3[p]); r4[p] = a; }
    }
    __syncthreads();
    if (tid < 64)
        r3[tid] = (tid < 16) ? in3[tid] : fadd(in3[tid], r4[(tid >> 4) - 1]);
    __syncthreads();
    r2s[tid] = (tid < 16) ? in2[tid] : fadd(in2[tid], r3[(tid >> 4) - 1]);
    __syncthreads();

    float E2 = (tid == 0) ? 0.0f : r2s[tid - 1];
    g_E2t[((n * NJ + tid) << 4) + h] = E2;
}

// ---------------------------------------------------------------------------
// Oscillator: 4 threads per level-0 tile, 4 harmonics each. Phase chain
// (leaf/run/dt/theta/CW) VERBATIM; k = rintf(dt) (provably equiv mod 2pi);
// amp & accumulate as single FMAs (amplitude-only rounding).
// ---------------------------------------------------------------------------
__global__ void __launch_bounds__(256) osc_kernel(const float* __restrict__ f0raw,
                                                  float* __restrict__ out) {
    __shared__ float sA[NH * LFR];
    __shared__ float sf0[LFR];
    __shared__ float stage[64 * 17];
    int n = blockIdx.y;
    int tid = threadIdx.x;
    {
        const float4* src = (const float4*)(g_A + n * NH * LFR);
        float4* dst = (float4*)sA;
        for (int i = tid; i < NH * LFR / 4; i += 256) dst[i] = src[i];
    }
    if (tid < LFR) sf0[tid] = fmaxf(f0raw[n * LFR + tid], 20.0f);
    __syncthreads();

    int ql = tid >> 2;          // tile within block (0..63)
    int hq = tid & 3;           // harmonic quad (h = 4*hq .. 4*hq+3)
    int q = blockIdx.x * 64 + ql;
    int t0 = q * 16;

    int i0, i1; float w0, omw0;
    coords(t0, i0, i1, w0, omw0);
    float i0f = (float)i0;
    float v0 = sf0[i0], v1 = sf0[i1];

    float Ev[4], run[4], a0[4], da[4];
    if (q == 0) {
#pragma unroll
        for (int i = 0; i < 4; i++) Ev[i] = 0.0f;
    } else {
        float4 p1 = *(const float4*)&g_P1[((n * NT + q - 1) << 4) + hq * 4];
        float4 e2 = *(const float4*)&g_E2t[((n * NJ + ((q - 1) >> 4)) << 4) + hq * 4];
        Ev[0] = fadd(p1.x, e2.x);
        Ev[1] = fadd(p1.y, e2.y);
        Ev[2] = fadd(p1.z, e2.z);
        Ev[3] = fadd(p1.w, e2.w);
    }
#pragma unroll
    for (int i = 0; i < 4; i++) {
        int h = hq * 4 + i;
        a0[i] = sA[h * LFR + i0];
        da[i] = sA[h * LFR + i1] - a0[i];
        run[i] = 0.0f;
    }
    float mh0 = (float)(hq * 4 + 1);
    const float C960 = (float)(1.0 / 960.0);

#pragma unroll
    for (int s = 0; s < 16; s++) {
        int t = t0 + s;
        float a = __fadd_rn((float)t, 0.5f);
        float pos = __fsub_rn(__fmul_rn(a, C960), 0.5f);
        pos = fminf(fmaxf(pos, 0.0f), 255.0f);
        float w = __fsub_rn(pos, i0f);
        float omw = __fsub_rn(1.0f, w);
        float f0u = fadd(fmul(v0, omw), fmul(v1, w));
        float part = 0.0f;
#pragma unroll
        for (int i = 0; i < 4; i++) {
            float mh = mh0 + (float)i;           // exact small ints
            float lv = leaf(f0u, mh);
            run[i] = fadd(run[i], lv);
            float dt = fadd(run[i], Ev[i]);
            float theta = __fmul_rn(TWOPI_F, dt);
            float k = rintf(dt);                 // == rint(theta/2pi) mod benign ±1
            float r = __fmaf_rn(-k, CW_A, theta);
            r = __fmaf_rn(-k, CW_B, r);
            r = __fmaf_rn(-k, CW_C, r);
            float sv = __sinf(r);
            float amp = __fmaf_rn(w, da[i], a0[i]);
            part = __fmaf_rn(sv, amp, part);
        }
        part = fadd(part, __shfl_xor_sync(0xffffffffu, part, 1));
        part = fadd(part, __shfl_xor_sync(0xffffffffu, part, 2));
        if (hq == 0) stage[ql * 17 + s] = __fmul_rn(part, 0.0625f);
    }
    __syncthreads();

    float* obase = out + n * L + blockIdx.x * 1024;
    for (int i = tid; i < 1024; i += 256)
        obase[i] = stage[(i >> 4) * 17 + (i & 15)];
}

// ---------------------------------------------------------------------------
extern "C" void kernel_launch(void* const* d_in, const int* in_sizes, int n_in,
                              void* d_out, int out_size) {
    const float* amps = (const float*)d_in[0];
    const float* f0 = (const float*)d_in[1];
    if (n_in >= 2 && in_sizes[0] == NB * LFR && in_sizes[1] == NB * NH * LFR) {
        const float* tmp = amps; amps = f0; f0 = tmp;
    }
    float* out = (float*)d_out;

    prep_exp<<<(NB * NH * LFR + 255) / 256, 256>>>(amps);
    scan1_kernel<<<dim3(NJ / 16, NB), 256>>>(f0);
    scan2_kernel<<<NB * NH, 960>>>();
    osc_kernel<<<dim3(NT / 64, NB), 256>>>(f0, out);
}

// round 12
// speedup vs baseline: 5.6952x; 1.0695x over previous
#include <cuda_runtime.h>
#include <math.h>

#define NB 16
#define NH 16
#define LFR 256
#define L 245760
#define NT 15360          // level-0 tiles (16 samples) per row
#define NJ 960            // level-1 tiles (256 samples) per row
#define TWOPI_F 6.28318530717958647692f
#define RINV ((float)(1.0 / 48000.0))   // fl32(1/48000)
#define CW_A 6.28125f
#define CW_B 1.9353071795864769e-3f
#define CW_C 6.3331253617479151e-11f
#define MAGIC 12582912.0f               // 1.5*2^23

typedef unsigned long long u64;

__device__ float g_A[NB * NH * LFR];    // exp(amps)
__device__ float g_P1[NB * NT * NH];    // inclusive level-1 prefixes, [n][q][h]
__device__ float g_S1[NB * NH * NJ];    // level-1 sums, [row][j]
__device__ float g_E2t[NB * NJ * NH];   // exclusive level-2 prefixes, [n][j][h]

static __device__ __forceinline__ float fadd(float a, float b) { return __fadd_rn(a, b); }
static __device__ __forceinline__ float fmul(float a, float b) { return __fmul_rn(a, b); }

// ---- f32x2 packed helpers (per-component RN) ----
static __device__ __forceinline__ u64 pk(float lo, float hi) {
    u64 r; asm("mov.b64 %0,{%1,%2};" : "=l"(r) : "f"(lo), "f"(hi)); return r;
}
static __device__ __forceinline__ void upk(u64 v, float& lo, float& hi) {
    asm("mov.b64 {%0,%1},%2;" : "=f"(lo), "=f"(hi) : "l"(v));
}
static __device__ __forceinline__ u64 f2add(u64 a, u64 b) {
    u64 r; asm("add.rn.f32x2 %0,%1,%2;" : "=l"(r) : "l"(a), "l"(b)); return r;
}
static __device__ __forceinline__ u64 f2mul(u64 a, u64 b) {
    u64 r; asm("mul.rn.f32x2 %0,%1,%2;" : "=l"(r) : "l"(a), "l"(b)); return r;
}
static __device__ __forceinline__ u64 f2fma(u64 a, u64 b, u64 c) {
    u64 r; asm("fma.rn.f32x2 %0,%1,%2,%3;" : "=l"(r) : "l"(a), "l"(b), "l"(c)); return r;
}

// reference leaf: fl( fl(f0up * h) * fl(1/48000) )
static __device__ __forceinline__ float leaf(float f0up, float mh) {
    return __fmul_rn(__fmul_rn(f0up, mh), RINV);
}

// reference-exact interp coords for sample t (mul-then-sub, no fma)
static __device__ __forceinline__ void coords(int t, int& i0, int& i1,
                                              float& w, float& omw) {
    const float C960 = (float)(1.0 / 960.0);
    float a = __fadd_rn((float)t, 0.5f);
    float pos = __fsub_rn(__fmul_rn(a, C960), 0.5f);
    pos = fminf(fmaxf(pos, 0.0f), 255.0f);
    i0 = (int)pos;
    i1 = min(i0 + 1, LFR - 1);
    w = __fsub_rn(pos, (float)i0);
    omw = __fsub_rn(1.0f, w);
}

// ---------------------------------------------------------------------------
__global__ void __launch_bounds__(256) prep_exp(const float* __restrict__ amps) {
    int i = blockIdx.x * 256 + threadIdx.x;
    if (i < NB * NH * LFR) g_A[i] = expf(amps[i]);
}

// ---------------------------------------------------------------------------
// scan1: VERBATIM R11 (scalar).
// ---------------------------------------------------------------------------
__global__ void __launch_bounds__(256) scan1_kernel(const float* __restrict__ f0raw) {
    __shared__ float sf0[LFR];
    __shared__ float smf[4096];
    int n = blockIdx.y;
    int tid = threadIdx.x;
    int baset = blockIdx.x * 4096;

    if (tid < LFR) sf0[tid] = fmaxf(f0raw[n * LFR + tid], 20.0f);
    __syncthreads();
    for (int i = tid; i < 4096; i += 256) {
        int t = baset + i;
        int i0, i1; float w, omw;
        coords(t, i0, i1, w, omw);
        smf[i] = fadd(fmul(sf0[i0], omw), fmul(sf0[i1], w));
    }
    __syncthreads();

    int jl = tid >> 4;
    int h = tid & 15;
    int jg = blockIdx.x * 16 + jl;
    float mh = (float)(h + 1);
    const float* base = smf + jl * 256;
    float acc1 = 0.0f;
#pragma unroll
    for (int ss = 0; ss < 16; ss++) {
        float a = 0.0f;
#pragma unroll
        for (int s = 0; s < 16; s++)
            a = fadd(a, leaf(base[ss * 16 + s], mh));
        acc1 = fadd(acc1, a);
        g_P1[((n * NT + jg * 16 + ss) << 4) + h] = acc1;
    }
    g_S1[(n * 16 + h) * NJ + jg] = acc1;
}

// ---------------------------------------------------------------------------
// scan2: VERBATIM R11 (scalar).
// ---------------------------------------------------------------------------
__global__ void __launch_bounds__(960) scan2_kernel() {
    __shared__ float s1[960];
    __shared__ float in2[960];
    __shared__ float r2s[960];
    __shared__ float s2[60];
    __shared__ float in3[64];
    __shared__ float s3[4];
    __shared__ float r4[4];
    __shared__ float r3[64];
    int row = blockIdx.x;
    int n = row >> 4, h = row & 15;
    int tid = threadIdx.x;

    s1[tid] = g_S1[row * NJ + tid];
    __syncthreads();

    if (tid < 60) {
        float a = 0.0f;
#pragma unroll
        for (int s = 0; s < 16; s++) { a = fadd(a, s1[tid * 16 + s]); in2[tid * 16 + s] = a; }
        s2[tid] = a;
    }
    __syncthreads();
    if (tid < 4) {
        float a = 0.0f;
#pragma unroll
        for (int s = 0; s < 16; s++) {
            int i = tid * 16 + s;
            float v = (i < 60) ? s2[i] : 0.0f;
            a = fadd(a, v);
            in3[i] = a;
        }
        s3[tid] = a;
    }
    __syncthreads();
    if (tid == 0) {
        float a = 0.0f;
#pragma unroll
        for (int p = 0; p < 4; p++) { a = fadd(a, s3[p]); r4[p] = a; }
    }
    __syncthreads();
    if (tid < 64)
        r3[tid] = (tid < 16) ? in3[tid] : fadd(in3[tid], r4[(tid >> 4) - 1]);
    __syncthreads();
    r2s[tid] = (tid < 16) ? in2[tid] : fadd(in2[tid], r3[(tid >> 4) - 1]);
    __syncthreads();

    float E2 = (tid == 0) ? 0.0f : r2s[tid - 1];
    g_E2t[((n * NJ + tid) << 4) + h] = E2;
}

// ---------------------------------------------------------------------------
// Oscillator: 4 threads per tile, 4 harmonics each as 2 f32x2 pairs.
// Phase chain semantics verbatim R11 per component; k via MAGIC (== rintf
// under RNE for |dt|<2^22); full 3-term CW; __sinf tail.
// ---------------------------------------------------------------------------
__global__ void __launch_bounds__(256) osc_kernel(const float* __restrict__ f0raw,
                                                  float* __restrict__ out) {
    __shared__ float sA[NH * LFR];
    __shared__ float sf0[LFR];
    __shared__ float stage[64 * 17];
    int n = blockIdx.y;
    int tid = threadIdx.x;
    {
        const float4* src = (const float4*)(g_A + n * NH * LFR);
        float4* dst = (float4*)sA;
        for (int i = tid; i < NH * LFR / 4; i += 256) dst[i] = src[i];
    }
    if (tid < LFR) sf0[tid] = fmaxf(f0raw[n * LFR + tid], 20.0f);
    __syncthreads();

    int ql = tid >> 2;
    int hq = tid & 3;
    int q = blockIdx.x * 64 + ql;
    int t0 = q * 16;

    int i0, i1; float w0, omw0;
    coords(t0, i0, i1, w0, omw0);
    float i0f = (float)i0;
    float v0 = sf0[i0], v1 = sf0[i1];

    u64 Ev2[2], run2[2], a02[2], da2[2], mh2[2];
    if (q == 0) {
        Ev2[0] = pk(0.0f, 0.0f); Ev2[1] = pk(0.0f, 0.0f);
    } else {
        float4 p1 = *(const float4*)&g_P1[((n * NT + q - 1) << 4) + hq * 4];
        float4 e2 = *(const float4*)&g_E2t[((n * NJ + ((q - 1) >> 4)) << 4) + hq * 4];
        Ev2[0] = pk(fadd(p1.x, e2.x), fadd(p1.y, e2.y));
        Ev2[1] = pk(fadd(p1.z, e2.z), fadd(p1.w, e2.w));
    }
#pragma unroll
    for (int p = 0; p < 2; p++) {
        int h = hq * 4 + p * 2;
        float a0l = sA[h * LFR + i0],       a0h = sA[(h + 1) * LFR + i0];
        float a1l = sA[h * LFR + i1],       a1h = sA[(h + 1) * LFR + i1];
        a02[p] = pk(a0l, a0h);
        da2[p] = pk(a1l - a0l, a1h - a0h);
        run2[p] = pk(0.0f, 0.0f);
        mh2[p] = pk((float)(h + 1), (float)(h + 2));
    }
    const u64 K2   = pk(RINV, RINV);
    const u64 TP2  = pk(TWOPI_F, TWOPI_F);
    const u64 MG2  = pk(MAGIC, MAGIC);
    const u64 NMG2 = pk(-MAGIC, -MAGIC);
    const u64 NCA2 = pk(-CW_A, -CW_A);
    const u64 NCB2 = pk(-CW_B, -CW_B);
    const u64 NCC2 = pk(-CW_C, -CW_C);
    const float C960 = (float)(1.0 / 960.0);

#pragma unroll
    for (int s = 0; s < 16; s++) {
        int t = t0 + s;
        float a = __fadd_rn((float)t, 0.5f);
        float pos = __fsub_rn(__fmul_rn(a, C960), 0.5f);
        pos = fminf(fmaxf(pos, 0.0f), 255.0f);
        float w = __fsub_rn(pos, i0f);
        float omw = __fsub_rn(1.0f, w);
        float f0u = fadd(fmul(v0, omw), fmul(v1, w));
        u64 f0u2 = pk(f0u, f0u);
        u64 w2 = pk(w, w);
        u64 acc2 = pk(0.0f, 0.0f);
#pragma unroll
        for (int p = 0; p < 2; p++) {
            u64 lv = f2mul(f2mul(f0u2, mh2[p]), K2);   // fl(fl(f0u*h)*R) per comp
            run2[p] = f2add(run2[p], lv);
            u64 dt = f2add(run2[p], Ev2[p]);
            u64 th = f2mul(TP2, dt);
            u64 k = f2add(f2add(dt, MG2), NMG2);        // rintf(dt) per comp (RNE)
            u64 r = f2fma(k, NCA2, th);
            r = f2fma(k, NCB2, r);
            r = f2fma(k, NCC2, r);
            float rl, rh; upk(r, rl, rh);
            float sl = __sinf(rl);
            float sh = __sinf(rh);
            u64 amp = f2fma(w2, da2[p], a02[p]);
            acc2 = f2fma(pk(sl, sh), amp, acc2);
        }
        float al, ah; upk(acc2, al, ah);
        float part = fadd(al, ah);
        part = fadd(part, __shfl_xor_sync(0xffffffffu, part, 1));
        part = fadd(part, __shfl_xor_sync(0xffffffffu, part, 2));
        if (hq == 0) stage[ql * 17 + s] = __fmul_rn(part, 0.0625f);
    }
    __syncthreads();

    float* obase = out + n * L + blockIdx.x * 1024;
    for (int i = tid; i < 1024; i += 256)
        obase[i] = stage[(i >> 4) * 17 + (i & 15)];
}

// ---------------------------------------------------------------------------
extern "C" void kernel_launch(void* const* d_in, const int* in_sizes, int n_in,
                              void* d_out, int out_size) {
    const float* amps = (const float*)d_in[0];
    const float* f0 = (const float*)d_in[1];
    if (n_in >= 2 && in_sizes[0] == NB * LFR && in_sizes[1] == NB * NH * LFR) {
        const float* tmp = amps; amps = f0; f0 = tmp;
    }
    float* out = (float*)d_out;

    prep_exp<<<(NB * NH * LFR + 255) / 256, 256>>>(amps);
    scan1_kernel<<<dim3(NJ / 16, NB), 256>>>(f0);
    scan2_kernel<<<NB * NH, 960>>>();
    osc_kernel<<<dim3(NT / 64, NB), 256>>>(f0, out);
}

// round 13
// speedup vs baseline: 6.0365x; 1.0599x over previous
#include <cuda_runtime.h>
#include <math.h>

#define NB 16
#define NH 16
#define LFR 256
#define L 245760
#define NT 15360          // level-0 tiles (16 samples) per row
#define NJ 960            // level-1 tiles (256 samples) per row
#define TWOPI_F 6.28318530717958647692f
#define RINV ((float)(1.0 / 48000.0))   // fl32(1/48000)
#define CW_A 6.28125f
#define CW_B 1.9353071795864769e-3f
#define MAGIC 12582912.0f               // 1.5*2^23

typedef unsigned long long u64;

__device__ float g_A[NB * NH * LFR];    // exp(amps)
__device__ float g_P1[NB * NT * NH];    // inclusive level-1 prefixes, [n][q][h]
__device__ float g_S1[NB * NH * NJ];    // level-1 sums, [row][j]
__device__ float g_E2t[NB * NJ * NH];   // exclusive level-2 prefixes, [n][j][h]

static __device__ __forceinline__ float fadd(float a, float b) { return __fadd_rn(a, b); }
static __device__ __forceinline__ float fmul(float a, float b) { return __fmul_rn(a, b); }

// ---- f32x2 packed helpers (osc only; never in scan) ----
static __device__ __forceinline__ u64 pk(float lo, float hi) {
    u64 r; asm("mov.b64 %0,{%1,%2};" : "=l"(r) : "f"(lo), "f"(hi)); return r;
}
static __device__ __forceinline__ void upk(u64 v, float& lo, float& hi) {
    asm("mov.b64 {%0,%1},%2;" : "=f"(lo), "=f"(hi) : "l"(v));
}
static __device__ __forceinline__ u64 f2add(u64 a, u64 b) {
    u64 r; asm("add.rn.f32x2 %0,%1,%2;" : "=l"(r) : "l"(a), "l"(b)); return r;
}
static __device__ __forceinline__ u64 f2mul(u64 a, u64 b) {
    u64 r; asm("mul.rn.f32x2 %0,%1,%2;" : "=l"(r) : "l"(a), "l"(b)); return r;
}
static __device__ __forceinline__ u64 f2fma(u64 a, u64 b, u64 c) {
    u64 r; asm("fma.rn.f32x2 %0,%1,%2,%3;" : "=l"(r) : "l"(a), "l"(b), "l"(c)); return r;
}

// reference leaf: fl( fl(f0up * h) * fl(1/48000) )
static __device__ __forceinline__ float leaf(float f0up, float mh) {
    return __fmul_rn(__fmul_rn(f0up, mh), RINV);
}

// reference-exact interp coords for sample t (mul-then-sub, no fma)
static __device__ __forceinline__ void coords(int t, int& i0, int& i1,
                                              float& w, float& omw) {
    const float C960 = (float)(1.0 / 960.0);
    float a = __fadd_rn((float)t, 0.5f);
    float pos = __fsub_rn(__fmul_rn(a, C960), 0.5f);
    pos = fminf(fmaxf(pos, 0.0f), 255.0f);
    i0 = (int)pos;
    i1 = min(i0 + 1, LFR - 1);
    w = __fsub_rn(pos, (float)i0);
    omw = __fsub_rn(1.0f, w);
}

// ---------------------------------------------------------------------------
// scan1: VERBATIM R12 scalar scan + distributed exp(amps) (fused prep).
// grid (60, NB) = 960 blocks; block b handles amps slice [b*69, ...).
// ---------------------------------------------------------------------------
__global__ void __launch_bounds__(256) scan1_kernel(const float* __restrict__ f0raw,
                                                    const float* __restrict__ amps) {
    __shared__ float sf0[LFR];
    __shared__ float smf[4096];
    int n = blockIdx.y;
    int tid = threadIdx.x;
    int baset = blockIdx.x * 4096;

    // fused prep_exp: 960 blocks cover 65536 elements
    {
        int bid = blockIdx.y * 60 + blockIdx.x;
        int i = bid * 256 + tid;                // wraps 65536/256 = 256 block-chunks
        if (bid < 256) g_A[i] = expf(amps[i]);
    }

    if (tid < LFR) sf0[tid] = fmaxf(f0raw[n * LFR + tid], 20.0f);
    __syncthreads();
    for (int i = tid; i < 4096; i += 256) {
        int t = baset + i;
        int i0, i1; float w, omw;
        coords(t, i0, i1, w, omw);
        smf[i] = fadd(fmul(sf0[i0], omw), fmul(sf0[i1], w));
    }
    __syncthreads();

    int jl = tid >> 4;
    int h = tid & 15;
    int jg = blockIdx.x * 16 + jl;
    float mh = (float)(h + 1);
    const float* base = smf + jl * 256;
    float acc1 = 0.0f;
#pragma unroll
    for (int ss = 0; ss < 16; ss++) {
        float a = 0.0f;
#pragma unroll
        for (int s = 0; s < 16; s++)
            a = fadd(a, leaf(base[ss * 16 + s], mh));
        acc1 = fadd(acc1, a);
        g_P1[((n * NT + jg * 16 + ss) << 4) + h] = acc1;
    }
    g_S1[(n * 16 + h) * NJ + jg] = acc1;
}

// ---------------------------------------------------------------------------
// scan2: VERBATIM R12 (scalar).
// ---------------------------------------------------------------------------
__global__ void __launch_bounds__(960) scan2_kernel() {
    __shared__ float s1[960];
    __shared__ float in2[960];
    __shared__ float r2s[960];
    __shared__ float s2[60];
    __shared__ float in3[64];
    __shared__ float s3[4];
    __shared__ float r4[4];
    __shared__ float r3[64];
    int row = blockIdx.x;
    int n = row >> 4, h = row & 15;
    int tid = threadIdx.x;

    s1[tid] = g_S1[row * NJ + tid];
    __syncthreads();

    if (tid < 60) {
        float a = 0.0f;
#pragma unroll
        for (int s = 0; s < 16; s++) { a = fadd(a, s1[tid * 16 + s]); in2[tid * 16 + s] = a; }
        s2[tid] = a;
    }
    __syncthreads();
    if (tid < 4) {
        float a = 0.0f;
#pragma unroll
        for (int s = 0; s < 16; s++) {
            int i = tid * 16 + s;
            float v = (i < 60) ? s2[i] : 0.0f;
            a = fadd(a, v);
            in3[i] = a;
        }
        s3[tid] = a;
    }
    __syncthreads();
    if (tid == 0) {
        float a = 0.0f;
#pragma unroll
        for (int p = 0; p < 4; p++) { a = fadd(a, s3[p]); r4[p] = a; }
    }
    __syncthreads();
    if (tid < 64)
        r3[tid] = (tid < 16) ? in3[tid] : fadd(in3[tid], r4[(tid >> 4) - 1]);
    __syncthreads();
    r2s[tid] = (tid < 16) ? in2[tid] : fadd(in2[tid], r3[(tid >> 4) - 1]);
    __syncthreads();

    float E2 = (tid == 0) ? 0.0f : r2s[tid - 1];
    g_E2t[((n * NJ + tid) << 4) + h] = E2;
}

// ---------------------------------------------------------------------------
// Oscillator: VERBATIM R12 except CW_C term dropped (k*CC <= 2e-6 rad).
// ---------------------------------------------------------------------------
__global__ void __launch_bounds__(256) osc_kernel(const float* __restrict__ f0raw,
                                                  float* __restrict__ out) {
    __shared__ float sA[NH * LFR];
    __shared__ float sf0[LFR];
    __shared__ float stage[64 * 17];
    int n = blockIdx.y;
    int tid = threadIdx.x;
    {
        const float4* src = (const float4*)(g_A + n * NH * LFR);
        float4* dst = (float4*)sA;
        for (int i = tid; i < NH * LFR / 4; i += 256) dst[i] = src[i];
    }
    if (tid < LFR) sf0[tid] = fmaxf(f0raw[n * LFR + tid], 20.0f);
    __syncthreads();

    int ql = tid >> 2;
    int hq = tid & 3;
    int q = blockIdx.x * 64 + ql;
    int t0 = q * 16;

    int i0, i1; float w0, omw0;
    coords(t0, i0, i1, w0, omw0);
    float i0f = (float)i0;
    float v0 = sf0[i0], v1 = sf0[i1];

    u64 Ev2[2], run2[2], a02[2], da2[2], mh2[2];
    if (q == 0) {
        Ev2[0] = pk(0.0f, 0.0f); Ev2[1] = pk(0.0f, 0.0f);
    } else {
        float4 p1 = *(const float4*)&g_P1[((n * NT + q - 1) << 4) + hq * 4];
        float4 e2 = *(const float4*)&g_E2t[((n * NJ + ((q - 1) >> 4)) << 4) + hq * 4];
        Ev2[0] = pk(fadd(p1.x, e2.x), fadd(p1.y, e2.y));
        Ev2[1] = pk(fadd(p1.z, e2.z), fadd(p1.w, e2.w));
    }
#pragma unroll
    for (int p = 0; p < 2; p++) {
        int h = hq * 4 + p * 2;
        float a0l = sA[h * LFR + i0],       a0h = sA[(h + 1) * LFR + i0];
        float a1l = sA[h * LFR + i1],       a1h = sA[(h + 1) * LFR + i1];
        a02[p] = pk(a0l, a0h);
        da2[p] = pk(a1l - a0l, a1h - a0h);
        run2[p] = pk(0.0f, 0.0f);
        mh2[p] = pk((float)(h + 1), (float)(h + 2));
    }
    const u64 K2   = pk(RINV, RINV);
    const u64 TP2  = pk(TWOPI_F, TWOPI_F);
    const u64 MG2  = pk(MAGIC, MAGIC);
    const u64 NMG2 = pk(-MAGIC, -MAGIC);
    const u64 NCA2 = pk(-CW_A, -CW_A);
    const u64 NCB2 = pk(-CW_B, -CW_B);
    const float C960 = (float)(1.0 / 960.0);

#pragma unroll
    for (int s = 0; s < 16; s++) {
        int t = t0 + s;
        float a = __fadd_rn((float)t, 0.5f);
        float pos = __fsub_rn(__fmul_rn(a, C960), 0.5f);
        pos = fminf(fmaxf(pos, 0.0f), 255.0f);
        float w = __fsub_rn(pos, i0f);
        float f0u = fadd(fmul(v0, __fsub_rn(1.0f, w)), fmul(v1, w));
        u64 f0u2 = pk(f0u, f0u);
        u64 w2 = pk(w, w);
        u64 acc2 = pk(0.0f, 0.0f);
#pragma unroll
        for (int p = 0; p < 2; p++) {
            u64 lv = f2mul(f2mul(f0u2, mh2[p]), K2);   // fl(fl(f0u*h)*R) per comp
            run2[p] = f2add(run2[p], lv);
            u64 dt = f2add(run2[p], Ev2[p]);
            u64 th = f2mul(TP2, dt);
            u64 k = f2add(f2add(dt, MG2), NMG2);        // rintf(dt) per comp (RNE)
            u64 r = f2fma(k, NCA2, th);
            r = f2fma(k, NCB2, r);
            float rl, rh; upk(r, rl, rh);
            float sl = __sinf(rl);
            float sh = __sinf(rh);
            u64 amp = f2fma(w2, da2[p], a02[p]);
            acc2 = f2fma(pk(sl, sh), amp, acc2);
        }
        float al, ah; upk(acc2, al, ah);
        float part = fadd(al, ah);
        part = fadd(part, __shfl_xor_sync(0xffffffffu, part, 1));
        part = fadd(part, __shfl_xor_sync(0xffffffffu, part, 2));
        if (hq == 0) stage[ql * 17 + s] = __fmul_rn(part, 0.0625f);
    }
    __syncthreads();

    float* obase = out + n * L + blockIdx.x * 1024;
    for (int i = tid; i < 1024; i += 256)
        obase[i] = stage[(i >> 4) * 17 + (i & 15)];
}

// ---------------------------------------------------------------------------
extern "C" void kernel_launch(void* const* d_in, const int* in_sizes, int n_in,
                              void* d_out, int out_size) {
    const float* amps = (const float*)d_in[0];
    const float* f0 = (const float*)d_in[1];
    if (n_in >= 2 && in_sizes[0] == NB * LFR && in_sizes[1] == NB * NH * LFR) {
        const float* tmp = amps; amps = f0; f0 = tmp;
    }
    float* out = (float*)d_out;

    scan1_kernel<<<dim3(NJ / 16, NB), 256>>>(f0, amps);
    scan2_kernel<<<NB * NH, 960>>>();
    osc_kernel<<<dim3(NT / 64, NB), 256>>>(f0, out);
}

// round 14
// speedup vs baseline: 6.5003x; 1.0768x over previous
#include <cuda_runtime.h>
#include <math.h>

#define NB 16
#define NH 16
#define LFR 256
#define L 245760
#define NT 15360          // level-0 tiles (16 samples) per row
#define NJ 960            // level-1 tiles (256 samples) per row
#define TWOPI_F 6.28318530717958647692f
#define RINV ((float)(1.0 / 48000.0))   // fl32(1/48000)
#define CW_A 6.28125f
#define CW_B 1.9353071795864769e-3f
#define MAGIC 12582912.0f               // 1.5*2^23

typedef unsigned long long u64;

__device__ float g_A[NB * NH * LFR];    // exp(amps)
__device__ float g_P1[NB * NT * NH];    // inclusive level-1 prefixes, [n][q][h]
__device__ float g_S1[NB * NH * NJ];    // level-1 sums, [row][j]
__device__ float g_E2t[NB * NJ * NH];   // exclusive level-2 prefixes, [n][j][h]

static __device__ __forceinline__ float fadd(float a, float b) { return __fadd_rn(a, b); }
static __device__ __forceinline__ float fmul(float a, float b) { return __fmul_rn(a, b); }

// ---- f32x2 packed helpers (osc only; never in scan) ----
static __device__ __forceinline__ u64 pk(float lo, float hi) {
    u64 r; asm("mov.b64 %0,{%1,%2};" : "=l"(r) : "f"(lo), "f"(hi)); return r;
}
static __device__ __forceinline__ void upk(u64 v, float& lo, float& hi) {
    asm("mov.b64 {%0,%1},%2;" : "=f"(lo), "=f"(hi) : "l"(v));
}
static __device__ __forceinline__ u64 f2add(u64 a, u64 b) {
    u64 r; asm("add.rn.f32x2 %0,%1,%2;" : "=l"(r) : "l"(a), "l"(b)); return r;
}
static __device__ __forceinline__ u64 f2mul(u64 a, u64 b) {
    u64 r; asm("mul.rn.f32x2 %0,%1,%2;" : "=l"(r) : "l"(a), "l"(b)); return r;
}
static __device__ __forceinline__ u64 f2fma(u64 a, u64 b, u64 c) {
    u64 r; asm("fma.rn.f32x2 %0,%1,%2,%3;" : "=l"(r) : "l"(a), "l"(b), "l"(c)); return r;
}

// reference leaf: fl( fl(f0up * h) * fl(1/48000) )
static __device__ __forceinline__ float leaf(float f0up, float mh) {
    return __fmul_rn(__fmul_rn(f0up, mh), RINV);
}

// reference-exact interp coords for sample t (mul-then-sub, no fma)
static __device__ __forceinline__ void coords(int t, int& i0, int& i1,
                                              float& w, float& omw) {
    const float C960 = (float)(1.0 / 960.0);
    float a = __fadd_rn((float)t, 0.5f);
    float pos = __fsub_rn(__fmul_rn(a, C960), 0.5f);
    pos = fminf(fmaxf(pos, 0.0f), 255.0f);
    i0 = (int)pos;
    i1 = min(i0 + 1, LFR - 1);
    w = __fsub_rn(pos, (float)i0);
    omw = __fsub_rn(1.0f, w);
}

// ---------------------------------------------------------------------------
// scan1: VERBATIM R13 (scalar) incl. fused exp(amps).
// ---------------------------------------------------------------------------
__global__ void __launch_bounds__(256) scan1_kernel(const float* __restrict__ f0raw,
                                                    const float* __restrict__ amps) {
    __shared__ float sf0[LFR];
    __shared__ float smf[4096];
    int n = blockIdx.y;
    int tid = threadIdx.x;
    int baset = blockIdx.x * 4096;

    {
        int bid = blockIdx.y * 60 + blockIdx.x;
        int i = bid * 256 + tid;
        if (bid < 256) g_A[i] = expf(amps[i]);
    }

    if (tid < LFR) sf0[tid] = fmaxf(f0raw[n * LFR + tid], 20.0f);
    __syncthreads();
    for (int i = tid; i < 4096; i += 256) {
        int t = baset + i;
        int i0, i1; float w, omw;
        coords(t, i0, i1, w, omw);
        smf[i] = fadd(fmul(sf0[i0], omw), fmul(sf0[i1], w));
    }
    __syncthreads();

    int jl = tid >> 4;
    int h = tid & 15;
    int jg = blockIdx.x * 16 + jl;
    float mh = (float)(h + 1);
    const float* base = smf + jl * 256;
    float acc1 = 0.0f;
#pragma unroll
    for (int ss = 0; ss < 16; ss++) {
        float a = 0.0f;
#pragma unroll
        for (int s = 0; s < 16; s++)
            a = fadd(a, leaf(base[ss * 16 + s], mh));
        acc1 = fadd(acc1, a);
        g_P1[((n * NT + jg * 16 + ss) << 4) + h] = acc1;
    }
    g_S1[(n * 16 + h) * NJ + jg] = acc1;
}

// ---------------------------------------------------------------------------
// scan2: VERBATIM R13 (scalar).
// ---------------------------------------------------------------------------
__global__ void __launch_bounds__(960) scan2_kernel() {
    __shared__ float s1[960];
    __shared__ float in2[960];
    __shared__ float r2s[960];
    __shared__ float s2[60];
    __shared__ float in3[64];
    __shared__ float s3[4];
    __shared__ float r4[4];
    __shared__ float r3[64];
    int row = blockIdx.x;
    int n = row >> 4, h = row & 15;
    int tid = threadIdx.x;

    s1[tid] = g_S1[row * NJ + tid];
    __syncthreads();

    if (tid < 60) {
        float a = 0.0f;
#pragma unroll
        for (int s = 0; s < 16; s++) { a = fadd(a, s1[tid * 16 + s]); in2[tid * 16 + s] = a; }
        s2[tid] = a;
    }
    __syncthreads();
    if (tid < 4) {
        float a = 0.0f;
#pragma unroll
        for (int s = 0; s < 16; s++) {
            int i = tid * 16 + s;
            float v = (i < 60) ? s2[i] : 0.0f;
            a = fadd(a, v);
            in3[i] = a;
        }
        s3[tid] = a;
    }
    __syncthreads();
    if (tid == 0) {
        float a = 0.0f;
#pragma unroll
        for (int p = 0; p < 4; p++) { a = fadd(a, s3[p]); r4[p] = a; }
    }
    __syncthreads();
    if (tid < 64)
        r3[tid] = (tid < 16) ? in3[tid] : fadd(in3[tid], r4[(tid >> 4) - 1]);
    __syncthreads();
    r2s[tid] = (tid < 16) ? in2[tid] : fadd(in2[tid], r3[(tid >> 4) - 1]);
    __syncthreads();

    float E2 = (tid == 0) ? 0.0f : r2s[tid - 1];
    g_E2t[((n * NJ + tid) << 4) + h] = E2;
}

// ---------------------------------------------------------------------------
// Oscillator: 2 threads per tile, 8 harmonics each (4 f32x2 pairs).
// Phase chain per component VERBATIM R13. One shuffle for the h-sum.
// ---------------------------------------------------------------------------
__global__ void __launch_bounds__(128) osc_kernel(const float* __restrict__ f0raw,
                                                  float* __restrict__ out) {
    __shared__ float sA[NH * LFR];
    __shared__ float sf0[LFR];
    __shared__ float stage[64 * 17];
    int n = blockIdx.y;
    int tid = threadIdx.x;
    {
        const float4* src = (const float4*)(g_A + n * NH * LFR);
        float4* dst = (float4*)sA;
        for (int i = tid; i < NH * LFR / 4; i += 128) dst[i] = src[i];
    }
    for (int i = tid; i < LFR; i += 128) sf0[i] = fmaxf(f0raw[n * LFR + i], 20.0f);
    __syncthreads();

    int ql = tid >> 1;          // tile within block (0..63)
    int hq = tid & 1;           // harmonic half (h = 8*hq .. 8*hq+7)
    int q = blockIdx.x * 64 + ql;
    int t0 = q * 16;

    int i0, i1; float w0, omw0;
    coords(t0, i0, i1, w0, omw0);
    float i0f = (float)i0;
    float v0 = sf0[i0], v1 = sf0[i1];

    u64 Ev2[4], run2[4], a02[4], da2[4], mh2[4];
    if (q == 0) {
#pragma unroll
        for (int p = 0; p < 4; p++) Ev2[p] = pk(0.0f, 0.0f);
    } else {
        const float* p1b = &g_P1[((n * NT + q - 1) << 4) + hq * 8];
        const float* e2b = &g_E2t[((n * NJ + ((q - 1) >> 4)) << 4) + hq * 8];
        float4 p1a = *(const float4*)p1b,       p1c = *(const float4*)(p1b + 4);
        float4 e2a = *(const float4*)e2b,       e2c = *(const float4*)(e2b + 4);
        Ev2[0] = pk(fadd(p1a.x, e2a.x), fadd(p1a.y, e2a.y));
        Ev2[1] = pk(fadd(p1a.z, e2a.z), fadd(p1a.w, e2a.w));
        Ev2[2] = pk(fadd(p1c.x, e2c.x), fadd(p1c.y, e2c.y));
        Ev2[3] = pk(fadd(p1c.z, e2c.z), fadd(p1c.w, e2c.w));
    }
#pragma unroll
    for (int p = 0; p < 4; p++) {
        int h = hq * 8 + p * 2;
        float a0l = sA[h * LFR + i0],       a0h = sA[(h + 1) * LFR + i0];
        float a1l = sA[h * LFR + i1],       a1h = sA[(h + 1) * LFR + i1];
        a02[p] = pk(a0l, a0h);
        da2[p] = pk(a1l - a0l, a1h - a0h);
        run2[p] = pk(0.0f, 0.0f);
        mh2[p] = pk((float)(h + 1), (float)(h + 2));
    }
    const u64 K2   = pk(RINV, RINV);
    const u64 TP2  = pk(TWOPI_F, TWOPI_F);
    const u64 MG2  = pk(MAGIC, MAGIC);
    const u64 NMG2 = pk(-MAGIC, -MAGIC);
    const u64 NCA2 = pk(-CW_A, -CW_A);
    const u64 NCB2 = pk(-CW_B, -CW_B);
    const float C960 = (float)(1.0 / 960.0);

#pragma unroll
    for (int s = 0; s < 16; s++) {
        int t = t0 + s;
        float a = __fadd_rn((float)t, 0.5f);
        float pos = __fsub_rn(__fmul_rn(a, C960), 0.5f);
        pos = fminf(fmaxf(pos, 0.0f), 255.0f);
        float w = __fsub_rn(pos, i0f);
        float f0u = fadd(fmul(v0, __fsub_rn(1.0f, w)), fmul(v1, w));
        u64 f0u2 = pk(f0u, f0u);
        u64 w2 = pk(w, w);
        u64 acc2 = pk(0.0f, 0.0f);
#pragma unroll
        for (int p = 0; p < 4; p++) {
            u64 lv = f2mul(f2mul(f0u2, mh2[p]), K2);   // fl(fl(f0u*h)*R) per comp
            run2[p] = f2add(run2[p], lv);
            u64 dt = f2add(run2[p], Ev2[p]);
            u64 th = f2mul(TP2, dt);
            u64 k = f2add(f2add(dt, MG2), NMG2);        // rintf(dt) per comp (RNE)
            u64 r = f2fma(k, NCA2, th);
            r = f2fma(k, NCB2, r);
            float rl, rh; upk(r, rl, rh);
            float sl = __sinf(rl);
            float sh = __sinf(rh);
            u64 amp = f2fma(w2, da2[p], a02[p]);
            acc2 = f2fma(pk(sl, sh), amp, acc2);
        }
        float al, ah; upk(acc2, al, ah);
        float part = fadd(al, ah);
        part = fadd(part, __shfl_xor_sync(0xffffffffu, part, 1));
        if (hq == 0) stage[ql * 17 + s] = __fmul_rn(part, 0.0625f);
    }
    __syncthreads();

    float* obase = out + n * L + blockIdx.x * 1024;
    for (int i = tid; i < 1024; i += 128)
        obase[i] = stage[(i >> 4) * 17 + (i & 15)];
}

// ---------------------------------------------------------------------------
extern "C" void kernel_launch(void* const* d_in, const int* in_sizes, int n_in,
                              void* d_out, int out_size) {
    const float* amps = (const float*)d_in[0];
    const float* f0 = (const float*)d_in[1];
    if (n_in >= 2 && in_sizes[0] == NB * LFR && in_sizes[1] == NB * NH * LFR) {
        const float* tmp = amps; amps = f0; f0 = tmp;
    }
    float* out = (float*)d_out;

    scan1_kernel<<<dim3(NJ / 16, NB), 256>>>(f0, amps);
    scan2_kernel<<<NB * NH, 960>>>();
    osc_kernel<<<dim3(NT / 64, NB), 128>>>(f0, out);
}